// round 16
// baseline (speedup 1.0000x reference)
#include <cuda_runtime.h>
#include <math.h>

#define BSZ 2
#define SEQ 2048
#define EMB 1024
#define NH  16
#define NKV 4
#define HDM 64
#define WIN 256

// ---------------- scratch (no allocations allowed) ----------------
__device__ float g_qp[BSZ*SEQ*EMB];        // x @ Wq^T
__device__ float g_kp[BSZ*SEQ*NKV*HDM];    // x @ Wk^T
__device__ float g_vp[BSZ*SEQ*NKV*HDM];    // x @ Wv^T
__device__ float g_q [BSZ*NH*SEQ*HDM];     // normed+roped+scaled q  [b][h][s][d]
__device__ float g_k [BSZ*NKV*SEQ*HDM];    // normed+roped k         [b][g][s][d]
__device__ float g_y [BSZ*SEQ*NH*HDM];     // attention out [b][s][h][d]
__device__ float g_wmix[EMB*EMB];          // pair-mixed Wo
__device__ float g_cos[SEQ*32];
__device__ float g_sin[SEQ*32];

__device__ __forceinline__ unsigned f2tf32(float f) {
    unsigned o;
    asm("cvt.rna.tf32.f32 %0, %1;" : "=r"(o) : "f"(f));
    return o;
}

#define MMA_TF32(c, a, b)                                                     \
    asm volatile(                                                             \
        "mma.sync.aligned.m16n8k8.row.col.f32.tf32.tf32.f32 "                 \
        "{%0,%1,%2,%3}, {%4,%5,%6,%7}, {%8,%9}, {%0,%1,%2,%3};"               \
        : "+f"((c)[0]), "+f"((c)[1]), "+f"((c)[2]), "+f"((c)[3])              \
        : "r"((a)[0]), "r"((a)[1]), "r"((a)[2]), "r"((a)[3]),                 \
          "r"((b)[0]), "r"((b)[1]))

// ---------------- rope tables + Wo premix (one launch) ----------------
__global__ void misc_kernel(const float* __restrict__ Wo,
                            const float* __restrict__ pm) {
    if (blockIdx.x < 256) {
        int idx = blockIdx.x * 256 + threadIdx.x;
        int s = idx >> 5, l = idx & 31;
        double inv = exp(-(double)l * (9.210340371976184 / 32.0)); // ln(10000)
        double a = (double)s * inv;
        g_cos[idx] = (float)cos(a);
        g_sin[idx] = (float)sin(a);
    } else {
        int widx = (blockIdx.x - 256) * 256 + threadIdx.x;   // over 1024*1024
        int c = widx & 1023;
        int n = widx >> 10;
        int p = c >> 7, rem = c & 127;
        int i = rem >> 6, d = rem & 63;
        float w0 = Wo[(size_t)n * EMB + (p << 7) + d];
        float w1 = Wo[(size_t)n * EMB + (p << 7) + 64 + d];
        g_wmix[widx] = pm[(p << 2) + i] * w0 + pm[(p << 2) + 2 + i] * w1;
    }
}

// ------- tf32 tensor-core GEMM (3-way segmented, double-buffered) --------
// C[M,Nseg] = A[M,K] @ Wseg[Nseg,K]^T. 128x128 tile, BK=16 x 2 stages.
#define SSTR 24
#define GBUF (128 * SSTR)

__global__ __launch_bounds__(256) void gemm_tc(
    const float* __restrict__ A,
    const float* __restrict__ W0, float* __restrict__ C0, int N0,
    const float* __restrict__ W1, float* __restrict__ C1, int N1,
    const float* __restrict__ W2, float* __restrict__ C2, int N2,
    int K)
{
    const float* W; float* C; int NC, nb;
    {
        int bx = blockIdx.x;
        int n0b = N0 >> 7, n1b = N1 >> 7;
        if (bx < n0b)            { W = W0; C = C0; NC = N0; nb = bx; }
        else if (bx < n0b + n1b) { W = W1; C = C1; NC = N1; nb = bx - n0b; }
        else                     { W = W2; C = C2; NC = N2; nb = bx - n0b - n1b; }
    }

    extern __shared__ unsigned smg[];
    unsigned* sA = smg;              // [2][GBUF]
    unsigned* sW = smg + 2 * GBUF;   // [2][GBUF]

    const int t    = threadIdx.x;
    const int lane = t & 31, warp = t >> 5;
    const int wm = warp >> 2, wn = warp & 3;
    const int gr = lane >> 2, tg = lane & 3;
    const int m0 = blockIdx.y << 7, n0 = nb << 7;

    const int ar = t >> 2;
    const int ac = (t & 3) << 2;
    const float* Ap = A + (size_t)(m0 + ar) * K + ac;
    const float* Wp = W + (size_t)(n0 + ar) * K + ac;

    int scol[4];
#pragma unroll
    for (int j = 0; j < 4; j++) {
        int kl = ac + j;
        scol[j] = ((kl >> 3) << 3) + ((kl & 3) << 1) + ((kl >> 2) & 1);
    }

    float c[4][4][4] = {};
    float4 a0v, a1v, w0v, w1v;

#define G_LOAD(k0)                                                 \
    do {                                                           \
        a0v = *(const float4*)(Ap + (k0));                         \
        a1v = *(const float4*)(Ap + (size_t)64 * K + (k0));        \
        w0v = *(const float4*)(Wp + (k0));                         \
        w1v = *(const float4*)(Wp + (size_t)64 * K + (k0));        \
    } while (0)

#define G_STAGE(buf)                                               \
    do {                                                           \
        unsigned* bA = sA + (buf) * GBUF;                          \
        unsigned* bW = sW + (buf) * GBUF;                          \
        float av0[4] = {a0v.x, a0v.y, a0v.z, a0v.w};               \
        float av1[4] = {a1v.x, a1v.y, a1v.z, a1v.w};               \
        float wv0[4] = {w0v.x, w0v.y, w0v.z, w0v.w};               \
        float wv1[4] = {w1v.x, w1v.y, w1v.z, w1v.w};               \
        _Pragma("unroll")                                          \
        for (int j = 0; j < 4; j++) {                              \
            bA[ar * SSTR + scol[j]]        = f2tf32(av0[j]);       \
            bA[(ar + 64) * SSTR + scol[j]] = f2tf32(av1[j]);       \
            bW[ar * SSTR + scol[j]]        = f2tf32(wv0[j]);       \
            bW[(ar + 64) * SSTR + scol[j]] = f2tf32(wv1[j]);       \
        }                                                          \
    } while (0)

    const int nit = K >> 4;
    G_LOAD(0);
    G_STAGE(0);
    if (nit > 1) G_LOAD(16);
    __syncthreads();

    for (int it = 0;; it++) {
        const int cur = it & 1;
        if (it + 1 < nit) {
            G_STAGE(cur ^ 1);
            if (it + 2 < nit) G_LOAD((it + 2) << 4);
        }
        const unsigned* bA = sA + cur * GBUF;
        const unsigned* bW = sW + cur * GBUF;
#pragma unroll
        for (int kk = 0; kk < 2; kk++) {
            unsigned a[4][4];
            unsigned b[4][2];
            const int kb = (kk << 3) + (tg << 1);
#pragma unroll
            for (int mi = 0; mi < 4; mi++) {
                int r = (wm << 6) + (mi << 4) + gr;
                uint2 lo = *(const uint2*)&bA[r * SSTR + kb];
                uint2 hi = *(const uint2*)&bA[(r + 8) * SSTR + kb];
                a[mi][0] = lo.x; a[mi][1] = hi.x; a[mi][2] = lo.y; a[mi][3] = hi.y;
            }
#pragma unroll
            for (int ni = 0; ni < 4; ni++) {
                int n = (wn << 5) + (ni << 3) + gr;
                uint2 bv = *(const uint2*)&bW[n * SSTR + kb];
                b[ni][0] = bv.x; b[ni][1] = bv.y;
            }
#pragma unroll
            for (int mi = 0; mi < 4; mi++)
#pragma unroll
                for (int ni = 0; ni < 4; ni++)
                    MMA_TF32(c[mi][ni], a[mi], b[ni]);
        }
        if (it + 1 == nit) break;
        __syncthreads();
    }

#pragma unroll
    for (int mi = 0; mi < 4; mi++) {
#pragma unroll
        for (int ni = 0; ni < 4; ni++) {
            int row = m0 + (wm << 6) + (mi << 4) + gr;
            int col = n0 + (wn << 5) + (ni << 3) + (tg << 1);
            *(float2*)&C[(size_t)row * NC + col] =
                make_float2(c[mi][ni][0], c[mi][ni][1]);
            *(float2*)&C[(size_t)(row + 8) * NC + col] =
                make_float2(c[mi][ni][2], c[mi][ni][3]);
        }
    }
}

// ---------------- rmsnorm + rope + gain ----------------
__global__ __launch_bounds__(256) void prep_kernel(const float* __restrict__ qgain)
{
    const int gw   = (blockIdx.x * 256 + threadIdx.x) >> 5;
    const int lane = threadIdx.x & 31;
    const int NQ = BSZ * SEQ * NH;
    const int NK = BSZ * SEQ * NKV;

    const float* in; float* out; float extra; int s;
    if (gw < NQ) {
        int h = gw & 15; int bs = gw >> 4;
        s = bs & (SEQ - 1); int b = bs >> 11;
        in  = g_qp + (size_t)bs * EMB + h * HDM;
        out = g_q  + ((size_t)(b * NH + h) * SEQ + s) * HDM;
        extra = qgain[h] * 0.125f;
    } else {
        int kw = gw - NQ;
        if (kw >= NK) return;
        int g = kw & 3; int bs = kw >> 2;
        s = bs & (SEQ - 1); int b = bs >> 11;
        in  = g_kp + (size_t)bs * (NKV * HDM) + g * HDM;
        out = g_k  + ((size_t)(b * NKV + g) * SEQ + s) * HDM;
        extra = 1.f;
    }
    float v1 = in[lane], v2 = in[lane + 32];
    float ss = v1 * v1 + v2 * v2;
#pragma unroll
    for (int o = 16; o; o >>= 1) ss += __shfl_xor_sync(0xffffffffu, ss, o);
    float r = rsqrtf(ss * (1.f / HDM) + 1e-6f) * extra;
    float c  = g_cos[s * 32 + lane];
    float sn = g_sin[s * 32 + lane];
    out[lane]      = (v1 * c + v2 * sn) * r;
    out[lane + 32] = (v2 * c - v1 * sn) * r;
}

// ---------------- tensor-core windowed flash attention (R15) -------------
#define ASTR 68

__global__ __launch_bounds__(256, 2) void attn_tc()
{
    extern __shared__ unsigned smu[];
    unsigned* sQ = smu;                    // [128][68]
    unsigned* sK = sQ + 128 * ASTR;        // [64][68]
    unsigned* sV = sK + 64 * ASTR;         // [64][68]

    const int tid  = threadIdx.x;
    const int lane = tid & 31, w = tid >> 5;
    const int gr = lane >> 2, tg = lane & 3;
    const int bh = blockIdx.y;
    const int b = bh >> 4, h = bh & 15, g = h >> 2;
    const int q0 = blockIdx.x << 7;

    // stage Q tile as tf32
    const float* Qg = g_q + ((size_t)(b * NH + h) * SEQ + q0) * HDM;
    for (int i = tid; i < 128 * 16; i += 256) {
        int r = i >> 4, d4 = (i & 15) << 2;
        float4 v = *(const float4*)(Qg + r * HDM + d4);
        unsigned* dst = sQ + r * ASTR + d4;
        dst[0] = f2tf32(v.x); dst[1] = f2tf32(v.y);
        dst[2] = f2tf32(v.z); dst[3] = f2tf32(v.w);
    }

    float m0 = -1e30f, m1 = -1e30f, l0 = 0.f, l1 = 0.f;
    float O[8][4];
#pragma unroll
    for (int ni = 0; ni < 8; ni++)
#pragma unroll
        for (int j = 0; j < 4; j++) O[ni][j] = 0.f;

    const int qw = q0 + (w << 4);
    const int qr0 = qw + gr;

    const float* Kg0 = g_k  + (size_t)(b * NKV + g) * SEQ * HDM;
    const float* Vg0 = g_vp + (size_t)b * SEQ * (NKV * HDM) + g * HDM;

    for (int kt0 = q0 - 256; kt0 <= q0 + 64; kt0 += 64) {
        if (kt0 < 0) continue;
        __syncthreads();
        const float* Kg = Kg0 + (size_t)kt0 * HDM;
        const float* Vg = Vg0 + (size_t)kt0 * (NKV * HDM);
        for (int i = tid; i < 64 * 16; i += 256) {
            int r = i >> 4, d4 = (i & 15) << 2;
            float4 kv = *(const float4*)(Kg + r * HDM + d4);
            unsigned* dk = sK + r * ASTR + d4;
            dk[0] = f2tf32(kv.x); dk[1] = f2tf32(kv.y);
            dk[2] = f2tf32(kv.z); dk[3] = f2tf32(kv.w);
            float4 vv = *(const float4*)(Vg + r * (NKV * HDM) + d4);
            unsigned* dv = sV + r * ASTR + d4;
            dv[0] = f2tf32(vv.x); dv[1] = f2tf32(vv.y);
            dv[2] = f2tf32(vv.z); dv[3] = f2tf32(vv.w);
        }
        __syncthreads();

        // warp-uniform skips: future tile OR fully window-expired tile
        if (kt0 > qw + 15) continue;
        if (kt0 + 63 + WIN <= qw) continue;

        // ---- S = Q K^T ----
        float c[8][4] = {};
#pragma unroll
        for (int kk = 0; kk < 8; kk++) {
            const int kb = (kk << 3) + tg;
            unsigned a[4];
            a[0] = sQ[(qw - q0 + gr) * ASTR + kb];
            a[1] = sQ[(qw - q0 + gr + 8) * ASTR + kb];
            a[2] = sQ[(qw - q0 + gr) * ASTR + kb + 4];
            a[3] = sQ[(qw - q0 + gr + 8) * ASTR + kb + 4];
#pragma unroll
            for (int ni = 0; ni < 8; ni++) {
                unsigned bb[2];
                bb[0] = sK[((ni << 3) + gr) * ASTR + kb];
                bb[1] = sK[((ni << 3) + gr) * ASTR + kb + 4];
                MMA_TF32(c[ni], a, bb);
            }
        }

        // ---- mask + warp-local online softmax ----
        const bool full = (kt0 + 63 <= qw) && (qw + 15 - kt0 < WIN);
        float rx0 = -1e30f, rx1 = -1e30f;
#pragma unroll
        for (int ni = 0; ni < 8; ni++) {
            if (!full) {
                int c0 = kt0 + (ni << 3) + (tg << 1);
                int q_0 = qr0, q_1 = qr0 + 8;
                if (c0 > q_0   || q_0 - c0 >= WIN)     c[ni][0] = -1e30f;
                if (c0+1 > q_0 || q_0 - (c0+1) >= WIN) c[ni][1] = -1e30f;
                if (c0 > q_1   || q_1 - c0 >= WIN)     c[ni][2] = -1e30f;
                if (c0+1 > q_1 || q_1 - (c0+1) >= WIN) c[ni][3] = -1e30f;
            }
            rx0 = fmaxf(rx0, fmaxf(c[ni][0], c[ni][1]));
            rx1 = fmaxf(rx1, fmaxf(c[ni][2], c[ni][3]));
        }
        rx0 = fmaxf(rx0, __shfl_xor_sync(0xffffffffu, rx0, 1));
        rx0 = fmaxf(rx0, __shfl_xor_sync(0xffffffffu, rx0, 2));
        rx1 = fmaxf(rx1, __shfl_xor_sync(0xffffffffu, rx1, 1));
        rx1 = fmaxf(rx1, __shfl_xor_sync(0xffffffffu, rx1, 2));

        float mn0 = fmaxf(m0, rx0), mn1 = fmaxf(m1, rx1);
        float fac0 = __expf(m0 - mn0), fac1 = __expf(m1 - mn1);
        m0 = mn0; m1 = mn1;

        float s0 = 0.f, s1 = 0.f;
#pragma unroll
        for (int ni = 0; ni < 8; ni++) {
            float p0 = (c[ni][0] > -1e29f) ? __expf(c[ni][0] - mn0) : 0.f;
            float p1 = (c[ni][1] > -1e29f) ? __expf(c[ni][1] - mn0) : 0.f;
            float p2 = (c[ni][2] > -1e29f) ? __expf(c[ni][2] - mn1) : 0.f;
            float p3 = (c[ni][3] > -1e29f) ? __expf(c[ni][3] - mn1) : 0.f;
            s0 += p0 + p1; s1 += p2 + p3;
            c[ni][0] = p0; c[ni][1] = p1; c[ni][2] = p2; c[ni][3] = p3;
        }
        s0 += __shfl_xor_sync(0xffffffffu, s0, 1);
        s0 += __shfl_xor_sync(0xffffffffu, s0, 2);
        s1 += __shfl_xor_sync(0xffffffffu, s1, 1);
        s1 += __shfl_xor_sync(0xffffffffu, s1, 2);
        l0 = l0 * fac0 + s0;
        l1 = l1 * fac1 + s1;
#pragma unroll
        for (int ni = 0; ni < 8; ni++) {
            O[ni][0] *= fac0; O[ni][1] *= fac0;
            O[ni][2] *= fac1; O[ni][3] *= fac1;
        }

        // ---- O += P V ---- (P fragments via 4-lane shuffles)
        const int sl0 = (lane & ~3) | (tg >> 1);
        const int sl2 = sl0 + 2;
        const bool odd = tg & 1;
#pragma unroll
        for (int kk = 0; kk < 8; kk++) {
            float q00 = __shfl_sync(0xffffffffu, c[kk][0], sl0);
            float q01 = __shfl_sync(0xffffffffu, c[kk][1], sl0);
            float q10 = __shfl_sync(0xffffffffu, c[kk][2], sl0);
            float q11 = __shfl_sync(0xffffffffu, c[kk][3], sl0);
            float q20 = __shfl_sync(0xffffffffu, c[kk][0], sl2);
            float q21 = __shfl_sync(0xffffffffu, c[kk][1], sl2);
            float q30 = __shfl_sync(0xffffffffu, c[kk][2], sl2);
            float q31 = __shfl_sync(0xffffffffu, c[kk][3], sl2);
            unsigned a[4];
            a[0] = f2tf32(odd ? q01 : q00);
            a[1] = f2tf32(odd ? q11 : q10);
            a[2] = f2tf32(odd ? q21 : q20);
            a[3] = f2tf32(odd ? q31 : q30);
            const int kb = (kk << 3) + tg;
#pragma unroll
            for (int ni = 0; ni < 8; ni++) {
                unsigned bb[2];
                bb[0] = sV[kb * ASTR + (ni << 3) + gr];
                bb[1] = sV[(kb + 4) * ASTR + (ni << 3) + gr];
                MMA_TF32(O[ni], a, bb);
            }
        }
    }

    // epilogue: divide by l, write [b][s][h][d]
    float inv0 = 1.f / l0, inv1 = 1.f / l1;
#pragma unroll
    for (int ni = 0; ni < 8; ni++) {
        int col = (ni << 3) + (tg << 1);
        size_t base0 = (((size_t)b * SEQ + qr0) * NH + h) * HDM + col;
        size_t base1 = (((size_t)b * SEQ + qr0 + 8) * NH + h) * HDM + col;
        *(float2*)&g_y[base0] = make_float2(O[ni][0] * inv0, O[ni][1] * inv0);
        *(float2*)&g_y[base1] = make_float2(O[ni][2] * inv1, O[ni][3] * inv1);
    }
}

// ---------------- launch ----------------
extern "C" void kernel_launch(void* const* d_in, const int* in_sizes, int n_in,
                              void* d_out, int out_size)
{
    const float* x     = (const float*)d_in[0];
    const float* Wq    = (const float*)d_in[1];
    const float* Wk    = (const float*)d_in[2];
    const float* Wv    = (const float*)d_in[3];
    const float* Wo    = (const float*)d_in[4];
    const float* qgain = (const float*)d_in[5];
    const float* pm    = (const float*)d_in[6];
    float* out = (float*)d_out;

    void *qp, *kp, *vp, *y, *wmix;
    cudaGetSymbolAddress(&qp,   g_qp);
    cudaGetSymbolAddress(&kp,   g_kp);
    cudaGetSymbolAddress(&vp,   g_vp);
    cudaGetSymbolAddress(&y,    g_y);
    cudaGetSymbolAddress(&wmix, g_wmix);

    const int GEMM_SMEM = 4 * GBUF * 4;                  // 49152 B
    const int ATTN_SMEM = (128 + 64 + 64) * ASTR * 4;    // 69632 B
    cudaFuncSetAttribute(gemm_tc, cudaFuncAttributeMaxDynamicSharedMemorySize,
                         GEMM_SMEM);
    cudaFuncSetAttribute(attn_tc, cudaFuncAttributeMaxDynamicSharedMemorySize,
                         ATTN_SMEM);

    const int M = BSZ * SEQ;                 // 4096

    misc_kernel<<<256 + EMB * EMB / 256, 256>>>(Wo, pm);
    // fused Q/K/V projections: 8 + 2 + 2 = 12 column-blocks
    gemm_tc<<<dim3(12, M / 128), 256, GEMM_SMEM>>>(
        x,
        Wq, (float*)qp, EMB,
        Wk, (float*)kp, NKV * HDM,
        Wv, (float*)vp, NKV * HDM,
        EMB);
    prep_kernel<<<(BSZ * SEQ * (NH + NKV) * 32) / 256, 256>>>(qgain);
    attn_tc<<<dim3(SEQ / 128, BSZ * NH), 256, ATTN_SMEM>>>();
    // output projection with premixed Wo
    gemm_tc<<<dim3(8, M / 128), 256, GEMM_SMEM>>>(
        (const float*)y,
        (const float*)wmix, out, EMB,
        (const float*)wmix, out, EMB,
        (const float*)wmix, out, EMB,
        EMB);
}

// round 17
// speedup vs baseline: 1.0770x; 1.0770x over previous
#include <cuda_runtime.h>
#include <math.h>

#define BSZ 2
#define SEQ 2048
#define EMB 1024
#define NH  16
#define NKV 4
#define HDM 64
#define WIN 256

// ---------------- scratch (no allocations allowed) ----------------
__device__ float g_qp[BSZ*SEQ*EMB];        // x @ Wq^T
__device__ float g_kp[BSZ*SEQ*NKV*HDM];    // x @ Wk^T
__device__ float g_vp[BSZ*SEQ*NKV*HDM];    // x @ Wv^T
__device__ float g_q [BSZ*NH*SEQ*HDM];     // normed+roped+scaled q  [b][h][s][d]
__device__ float g_k [BSZ*NKV*SEQ*HDM];    // normed+roped k         [b][g][s][d]
__device__ float g_y [BSZ*SEQ*NH*HDM];     // attention out [b][s][h][d]
__device__ float g_wmix[EMB*EMB];          // pair-mixed Wo
__device__ float g_cos[SEQ*32];
__device__ float g_sin[SEQ*32];

__device__ __forceinline__ unsigned f2tf32(float f) {
    unsigned o;
    asm("cvt.rna.tf32.f32 %0, %1;" : "=r"(o) : "f"(f));
    return o;
}

#define MMA_TF32(c, a, b)                                                     \
    asm volatile(                                                             \
        "mma.sync.aligned.m16n8k8.row.col.f32.tf32.tf32.f32 "                 \
        "{%0,%1,%2,%3}, {%4,%5,%6,%7}, {%8,%9}, {%0,%1,%2,%3};"               \
        : "+f"((c)[0]), "+f"((c)[1]), "+f"((c)[2]), "+f"((c)[3])              \
        : "r"((a)[0]), "r"((a)[1]), "r"((a)[2]), "r"((a)[3]),                 \
          "r"((b)[0]), "r"((b)[1]))

// ---------------- rope tables + Wo premix (one launch) ----------------
__global__ void misc_kernel(const float* __restrict__ Wo,
                            const float* __restrict__ pm) {
    if (blockIdx.x < 256) {
        int idx = blockIdx.x * 256 + threadIdx.x;
        int s = idx >> 5, l = idx & 31;
        double inv = exp(-(double)l * (9.210340371976184 / 32.0)); // ln(10000)
        double a = (double)s * inv;
        g_cos[idx] = (float)cos(a);
        g_sin[idx] = (float)sin(a);
    } else {
        int widx = (blockIdx.x - 256) * 256 + threadIdx.x;   // over 1024*1024
        int c = widx & 1023;
        int n = widx >> 10;
        int p = c >> 7, rem = c & 127;
        int i = rem >> 6, d = rem & 63;
        float w0 = Wo[(size_t)n * EMB + (p << 7) + d];
        float w1 = Wo[(size_t)n * EMB + (p << 7) + 64 + d];
        g_wmix[widx] = pm[(p << 2) + i] * w0 + pm[(p << 2) + 2 + i] * w1;
    }
}

// ---------------- tf32 tensor-core GEMM (3-way segmented, R13) -----------
#define SSTR 24

__global__ __launch_bounds__(256) void gemm_tc(
    const float* __restrict__ A,
    const float* __restrict__ W0, float* __restrict__ C0, int N0,
    const float* __restrict__ W1, float* __restrict__ C1, int N1,
    const float* __restrict__ W2, float* __restrict__ C2, int N2,
    int K)
{
    const float* W; float* C; int NC, nb;
    {
        int bx = blockIdx.x;
        int n0b = N0 >> 7, n1b = N1 >> 7;
        if (bx < n0b)            { W = W0; C = C0; NC = N0; nb = bx; }
        else if (bx < n0b + n1b) { W = W1; C = C1; NC = N1; nb = bx - n0b; }
        else                     { W = W2; C = C2; NC = N2; nb = bx - n0b - n1b; }
    }

    __shared__ unsigned sA[128 * SSTR];
    __shared__ unsigned sW[128 * SSTR];

    const int t    = threadIdx.x;
    const int lane = t & 31, warp = t >> 5;
    const int wm = warp >> 2, wn = warp & 3;
    const int gr = lane >> 2, tg = lane & 3;
    const int m0 = blockIdx.y << 7, n0 = nb << 7;

    const int ar = t >> 2;
    const int ac = (t & 3) << 2;
    const float* Ap = A + (size_t)(m0 + ar) * K + ac;
    const float* Wp = W + (size_t)(n0 + ar) * K + ac;

    int scol[4];
#pragma unroll
    for (int j = 0; j < 4; j++) {
        int kl = ac + j;
        scol[j] = ((kl >> 3) << 3) + ((kl & 3) << 1) + ((kl >> 2) & 1);
    }

    float c[4][4][4] = {};

    float4 a0v = *(const float4*)(Ap);
    float4 a1v = *(const float4*)(Ap + (size_t)64 * K);
    float4 w0v = *(const float4*)(Wp);
    float4 w1v = *(const float4*)(Wp + (size_t)64 * K);

    for (int k0 = 16; ; k0 += 16) {
        __syncthreads();
        {
            float av0[4] = {a0v.x, a0v.y, a0v.z, a0v.w};
            float av1[4] = {a1v.x, a1v.y, a1v.z, a1v.w};
            float wv0[4] = {w0v.x, w0v.y, w0v.z, w0v.w};
            float wv1[4] = {w1v.x, w1v.y, w1v.z, w1v.w};
#pragma unroll
            for (int j = 0; j < 4; j++) {
                sA[ar * SSTR + scol[j]]        = f2tf32(av0[j]);
                sA[(ar + 64) * SSTR + scol[j]] = f2tf32(av1[j]);
                sW[ar * SSTR + scol[j]]        = f2tf32(wv0[j]);
                sW[(ar + 64) * SSTR + scol[j]] = f2tf32(wv1[j]);
            }
        }
        __syncthreads();

        if (k0 < K) {
            a0v = *(const float4*)(Ap + k0);
            a1v = *(const float4*)(Ap + (size_t)64 * K + k0);
            w0v = *(const float4*)(Wp + k0);
            w1v = *(const float4*)(Wp + (size_t)64 * K + k0);
        }

#pragma unroll
        for (int kk = 0; kk < 2; kk++) {
            unsigned a[4][4];
            unsigned b[4][2];
            const int kb = (kk << 3) + (tg << 1);
#pragma unroll
            for (int mi = 0; mi < 4; mi++) {
                int r = (wm << 6) + (mi << 4) + gr;
                uint2 lo = *(const uint2*)&sA[r * SSTR + kb];
                uint2 hi = *(const uint2*)&sA[(r + 8) * SSTR + kb];
                a[mi][0] = lo.x; a[mi][1] = hi.x; a[mi][2] = lo.y; a[mi][3] = hi.y;
            }
#pragma unroll
            for (int ni = 0; ni < 4; ni++) {
                int n = (wn << 5) + (ni << 3) + gr;
                uint2 bv = *(const uint2*)&sW[n * SSTR + kb];
                b[ni][0] = bv.x; b[ni][1] = bv.y;
            }
#pragma unroll
            for (int mi = 0; mi < 4; mi++)
#pragma unroll
                for (int ni = 0; ni < 4; ni++)
                    MMA_TF32(c[mi][ni], a[mi], b[ni]);
        }
        if (k0 >= K) break;
    }

#pragma unroll
    for (int mi = 0; mi < 4; mi++) {
#pragma unroll
        for (int ni = 0; ni < 4; ni++) {
            int row = m0 + (wm << 6) + (mi << 4) + gr;
            int col = n0 + (wn << 5) + (ni << 3) + (tg << 1);
            *(float2*)&C[(size_t)row * NC + col] =
                make_float2(c[mi][ni][0], c[mi][ni][1]);
            *(float2*)&C[(size_t)(row + 8) * NC + col] =
                make_float2(c[mi][ni][2], c[mi][ni][3]);
        }
    }
}

// ---------------- rmsnorm + rope + gain ----------------
__global__ __launch_bounds__(256) void prep_kernel(const float* __restrict__ qgain)
{
    const int gw   = (blockIdx.x * 256 + threadIdx.x) >> 5;
    const int lane = threadIdx.x & 31;
    const int NQ = BSZ * SEQ * NH;
    const int NK = BSZ * SEQ * NKV;

    const float* in; float* out; float extra; int s;
    if (gw < NQ) {
        int h = gw & 15; int bs = gw >> 4;
        s = bs & (SEQ - 1); int b = bs >> 11;
        in  = g_qp + (size_t)bs * EMB + h * HDM;
        out = g_q  + ((size_t)(b * NH + h) * SEQ + s) * HDM;
        extra = qgain[h] * 0.125f;
    } else {
        int kw = gw - NQ;
        if (kw >= NK) return;
        int g = kw & 3; int bs = kw >> 2;
        s = bs & (SEQ - 1); int b = bs >> 11;
        in  = g_kp + (size_t)bs * (NKV * HDM) + g * HDM;
        out = g_k  + ((size_t)(b * NKV + g) * SEQ + s) * HDM;
        extra = 1.f;
    }
    float v1 = in[lane], v2 = in[lane + 32];
    float ss = v1 * v1 + v2 * v2;
#pragma unroll
    for (int o = 16; o; o >>= 1) ss += __shfl_xor_sync(0xffffffffu, ss, o);
    float r = rsqrtf(ss * (1.f / HDM) + 1e-6f) * extra;
    float c  = g_cos[s * 32 + lane];
    float sn = g_sin[s * 32 + lane];
    out[lane]      = (v1 * c + v2 * sn) * r;
    out[lane + 32] = (v2 * c - v1 * sn) * r;
}

// ---------------- tensor-core windowed flash attention -------------------
// R15 compute + cp.async K/V pipeline: raw f32 K/V for tile i+1 streams into
// a smem staging buffer during tile i's compute; tf32 conversion reads smem.
#define ASTR 68
#define RKOFF (256 * ASTR)            // 17408 u32: raw K f32 [64][64]
#define RVOFF (RKOFF + 4096)          // raw V f32 [64][64]

__device__ __forceinline__ void cp16(unsigned dst, const void* src) {
    asm volatile("cp.async.cg.shared.global [%0], [%1], 16;"
                 :: "r"(dst), "l"(src));
}

__global__ __launch_bounds__(256, 2) void attn_tc()
{
    extern __shared__ unsigned smu[];
    unsigned* sQ = smu;                    // [128][68] tf32
    unsigned* sK = sQ + 128 * ASTR;        // [64][68] tf32
    unsigned* sV = sK + 64 * ASTR;         // [64][68] tf32
    float* rawK = (float*)(smu + RKOFF);   // [64][64] f32 staging
    float* rawV = (float*)(smu + RVOFF);   // [64][64] f32 staging

    const int tid  = threadIdx.x;
    const int lane = tid & 31, w = tid >> 5;
    const int gr = lane >> 2, tg = lane & 3;
    const int bh = blockIdx.y;
    const int b = bh >> 4, h = bh & 15, g = h >> 2;
    const int q0 = blockIdx.x << 7;

    unsigned sbase = (unsigned)__cvta_generic_to_shared(smu);
    const int crow = tid >> 4;             // 0..15
    const int ccol = (tid & 15) << 2;      // 0,4,..,60

    // stage Q tile as tf32
    const float* Qg = g_q + ((size_t)(b * NH + h) * SEQ + q0) * HDM;
    for (int i = tid; i < 128 * 16; i += 256) {
        int r = i >> 4, d4 = (i & 15) << 2;
        float4 v = *(const float4*)(Qg + r * HDM + d4);
        unsigned* dst = sQ + r * ASTR + d4;
        dst[0] = f2tf32(v.x); dst[1] = f2tf32(v.y);
        dst[2] = f2tf32(v.z); dst[3] = f2tf32(v.w);
    }

    float m0 = -1e30f, m1 = -1e30f, l0 = 0.f, l1 = 0.f;
    float O[8][4];
#pragma unroll
    for (int ni = 0; ni < 8; ni++)
#pragma unroll
        for (int j = 0; j < 4; j++) O[ni][j] = 0.f;

    const int qw = q0 + (w << 4);
    const int qr0 = qw + gr;

    const float* Kg0 = g_k  + (size_t)(b * NKV + g) * SEQ * HDM;
    const float* Vg0 = g_vp + (size_t)b * SEQ * (NKV * HDM) + g * HDM;

    const int ktFirst = (q0 >= 256) ? q0 - 256 : 0;
    const int ktLast  = q0 + 64;

#define A_CP(kt)                                                              \
    do {                                                                      \
        const float* Kg = Kg0 + (size_t)(kt) * HDM;                           \
        const float* Vg = Vg0 + (size_t)(kt) * (NKV * HDM);                   \
        _Pragma("unroll")                                                     \
        for (int j = 0; j < 4; j++) {                                         \
            int r = crow + (j << 4);                                          \
            cp16(sbase + (RKOFF + r * 64 + ccol) * 4, Kg + r * HDM + ccol);   \
            cp16(sbase + (RVOFF + r * 64 + ccol) * 4,                         \
                 Vg + r * (NKV * HDM) + ccol);                                \
        }                                                                     \
        asm volatile("cp.async.commit_group;");                               \
    } while (0)

    A_CP(ktFirst);

    for (int kt0 = ktFirst; kt0 <= ktLast; kt0 += 64) {
        asm volatile("cp.async.wait_group 0;");
        __syncthreads();   // raw tile ready; prior compute done with sK/sV

        // convert raw f32 (smem) -> tf32 sK/sV
#pragma unroll
        for (int j = 0; j < 4; j++) {
            int r = crow + (j << 4);
            float4 kv = *(const float4*)&rawK[r * 64 + ccol];
            unsigned* dk = sK + r * ASTR + ccol;
            dk[0] = f2tf32(kv.x); dk[1] = f2tf32(kv.y);
            dk[2] = f2tf32(kv.z); dk[3] = f2tf32(kv.w);
            float4 vv = *(const float4*)&rawV[r * 64 + ccol];
            unsigned* dv = sV + r * ASTR + ccol;
            dv[0] = f2tf32(vv.x); dv[1] = f2tf32(vv.y);
            dv[2] = f2tf32(vv.z); dv[3] = f2tf32(vv.w);
        }
        __syncthreads();   // conversion done: raw free for overwrite, sK/sV valid

        if (kt0 + 64 <= ktLast) A_CP(kt0 + 64);   // overlaps compute below

        // warp-uniform skips: future tile OR fully window-expired tile
        if (kt0 > qw + 15) continue;
        if (kt0 + 63 + WIN <= qw) continue;

        // ---- S = Q K^T ----
        float c[8][4] = {};
#pragma unroll
        for (int kk = 0; kk < 8; kk++) {
            const int kb = (kk << 3) + tg;
            unsigned a[4];
            a[0] = sQ[(qw - q0 + gr) * ASTR + kb];
            a[1] = sQ[(qw - q0 + gr + 8) * ASTR + kb];
            a[2] = sQ[(qw - q0 + gr) * ASTR + kb + 4];
            a[3] = sQ[(qw - q0 + gr + 8) * ASTR + kb + 4];
#pragma unroll
            for (int ni = 0; ni < 8; ni++) {
                unsigned bb[2];
                bb[0] = sK[((ni << 3) + gr) * ASTR + kb];
                bb[1] = sK[((ni << 3) + gr) * ASTR + kb + 4];
                MMA_TF32(c[ni], a, bb);
            }
        }

        // ---- mask + warp-local online softmax ----
        const bool full = (kt0 + 63 <= qw) && (qw + 15 - kt0 < WIN);
        float rx0 = -1e30f, rx1 = -1e30f;
#pragma unroll
        for (int ni = 0; ni < 8; ni++) {
            if (!full) {
                int c0 = kt0 + (ni << 3) + (tg << 1);
                int q_0 = qr0, q_1 = qr0 + 8;
                if (c0 > q_0   || q_0 - c0 >= WIN)     c[ni][0] = -1e30f;
                if (c0+1 > q_0 || q_0 - (c0+1) >= WIN) c[ni][1] = -1e30f;
                if (c0 > q_1   || q_1 - c0 >= WIN)     c[ni][2] = -1e30f;
                if (c0+1 > q_1 || q_1 - (c0+1) >= WIN) c[ni][3] = -1e30f;
            }
            rx0 = fmaxf(rx0, fmaxf(c[ni][0], c[ni][1]));
            rx1 = fmaxf(rx1, fmaxf(c[ni][2], c[ni][3]));
        }
        rx0 = fmaxf(rx0, __shfl_xor_sync(0xffffffffu, rx0, 1));
        rx0 = fmaxf(rx0, __shfl_xor_sync(0xffffffffu, rx0, 2));
        rx1 = fmaxf(rx1, __shfl_xor_sync(0xffffffffu, rx1, 1));
        rx1 = fmaxf(rx1, __shfl_xor_sync(0xffffffffu, rx1, 2));

        float mn0 = fmaxf(m0, rx0), mn1 = fmaxf(m1, rx1);
        float fac0 = __expf(m0 - mn0), fac1 = __expf(m1 - mn1);
        m0 = mn0; m1 = mn1;

        float s0 = 0.f, s1 = 0.f;
#pragma unroll
        for (int ni = 0; ni < 8; ni++) {
            float p0 = (c[ni][0] > -1e29f) ? __expf(c[ni][0] - mn0) : 0.f;
            float p1 = (c[ni][1] > -1e29f) ? __expf(c[ni][1] - mn0) : 0.f;
            float p2 = (c[ni][2] > -1e29f) ? __expf(c[ni][2] - mn1) : 0.f;
            float p3 = (c[ni][3] > -1e29f) ? __expf(c[ni][3] - mn1) : 0.f;
            s0 += p0 + p1; s1 += p2 + p3;
            c[ni][0] = p0; c[ni][1] = p1; c[ni][2] = p2; c[ni][3] = p3;
        }
        s0 += __shfl_xor_sync(0xffffffffu, s0, 1);
        s0 += __shfl_xor_sync(0xffffffffu, s0, 2);
        s1 += __shfl_xor_sync(0xffffffffu, s1, 1);
        s1 += __shfl_xor_sync(0xffffffffu, s1, 2);
        l0 = l0 * fac0 + s0;
        l1 = l1 * fac1 + s1;
#pragma unroll
        for (int ni = 0; ni < 8; ni++) {
            O[ni][0] *= fac0; O[ni][1] *= fac0;
            O[ni][2] *= fac1; O[ni][3] *= fac1;
        }

        // ---- O += P V ---- (P fragments via 4-lane shuffles)
        const int sl0 = (lane & ~3) | (tg >> 1);
        const int sl2 = sl0 + 2;
        const bool odd = tg & 1;
#pragma unroll
        for (int kk = 0; kk < 8; kk++) {
            float q00 = __shfl_sync(0xffffffffu, c[kk][0], sl0);
            float q01 = __shfl_sync(0xffffffffu, c[kk][1], sl0);
            float q10 = __shfl_sync(0xffffffffu, c[kk][2], sl0);
            float q11 = __shfl_sync(0xffffffffu, c[kk][3], sl0);
            float q20 = __shfl_sync(0xffffffffu, c[kk][0], sl2);
            float q21 = __shfl_sync(0xffffffffu, c[kk][1], sl2);
            float q30 = __shfl_sync(0xffffffffu, c[kk][2], sl2);
            float q31 = __shfl_sync(0xffffffffu, c[kk][3], sl2);
            unsigned a[4];
            a[0] = f2tf32(odd ? q01 : q00);
            a[1] = f2tf32(odd ? q11 : q10);
            a[2] = f2tf32(odd ? q21 : q20);
            a[3] = f2tf32(odd ? q31 : q30);
            const int kb = (kk << 3) + tg;
#pragma unroll
            for (int ni = 0; ni < 8; ni++) {
                unsigned bb[2];
                bb[0] = sV[kb * ASTR + (ni << 3) + gr];
                bb[1] = sV[(kb + 4) * ASTR + (ni << 3) + gr];
                MMA_TF32(O[ni], a, bb);
            }
        }
    }

    // epilogue: divide by l, write [b][s][h][d]
    float inv0 = 1.f / l0, inv1 = 1.f / l1;
#pragma unroll
    for (int ni = 0; ni < 8; ni++) {
        int col = (ni << 3) + (tg << 1);
        size_t base0 = (((size_t)b * SEQ + qr0) * NH + h) * HDM + col;
        size_t base1 = (((size_t)b * SEQ + qr0 + 8) * NH + h) * HDM + col;
        *(float2*)&g_y[base0] = make_float2(O[ni][0] * inv0, O[ni][1] * inv0);
        *(float2*)&g_y[base1] = make_float2(O[ni][2] * inv1, O[ni][3] * inv1);
    }
}

// ---------------- launch ----------------
extern "C" void kernel_launch(void* const* d_in, const int* in_sizes, int n_in,
                              void* d_out, int out_size)
{
    const float* x     = (const float*)d_in[0];
    const float* Wq    = (const float*)d_in[1];
    const float* Wk    = (const float*)d_in[2];
    const float* Wv    = (const float*)d_in[3];
    const float* Wo    = (const float*)d_in[4];
    const float* qgain = (const float*)d_in[5];
    const float* pm    = (const float*)d_in[6];
    float* out = (float*)d_out;

    void *qp, *kp, *vp, *y, *wmix;
    cudaGetSymbolAddress(&qp,   g_qp);
    cudaGetSymbolAddress(&kp,   g_kp);
    cudaGetSymbolAddress(&vp,   g_vp);
    cudaGetSymbolAddress(&y,    g_y);
    cudaGetSymbolAddress(&wmix, g_wmix);

    const int ATTN_SMEM = (RVOFF + 4096) * 4;    // 102400 B
    cudaFuncSetAttribute(attn_tc, cudaFuncAttributeMaxDynamicSharedMemorySize,
                         ATTN_SMEM);

    const int M = BSZ * SEQ;                 // 4096

    misc_kernel<<<256 + EMB * EMB / 256, 256>>>(Wo, pm);
    // fused Q/K/V projections: 8 + 2 + 2 = 12 column-blocks
    gemm_tc<<<dim3(12, M / 128), 256>>>(
        x,
        Wq, (float*)qp, EMB,
        Wk, (float*)kp, NKV * HDM,
        Wv, (float*)vp, NKV * HDM,
        EMB);
    prep_kernel<<<(BSZ * SEQ * (NH + NKV) * 32) / 256, 256>>>(qgain);
    attn_tc<<<dim3(SEQ / 128, BSZ * NH), 256, ATTN_SMEM>>>();
    // output projection with premixed Wo
    gemm_tc<<<dim3(8, M / 128), 256>>>(
        (const float*)y,
        (const float*)wmix, out, EMB,
        (const float*)wmix, out, EMB,
        (const float*)wmix, out, EMB,
        EMB);
}